// round 1
// baseline (speedup 1.0000x reference)
#include <cuda_runtime.h>

// Problem constants (fixed by the dataset)
static constexpr int KD = 4096;     // in_features
static constexpr int ND = 4096;     // out_features
static constexpr int GSIZE = 128;   // group size (KD / 32 groups)

// Dequantized weight scratch: [KD, ND] fp32 row-major (k-major, n contiguous).
// __device__ global = allowed allocation-free scratch.
__device__ float g_W[(size_t)KD * ND];

// ---------------------------------------------------------------------------
// Dequant: W[k][n] = scales[g[k]][n] * (q[k][n] - zp[g[k]][n])
// Fully vectorized: one int4/float4 quad per thread. HBM-bound (~128MB read,
// 64MB write -> ~25us).
// ---------------------------------------------------------------------------
__global__ __launch_bounds__(256) void dequant_kernel(
    const int* __restrict__ qw,
    const float* __restrict__ sc,
    const int* __restrict__ zp,
    const int* __restrict__ gidx)
{
    int idx = blockIdx.x * blockDim.x + threadIdx.x;   // over KD * ND/4
    int n4 = idx & (ND / 4 - 1);                       // quad index within row
    int k  = idx >> 10;                                // ND/4 = 1024 = 2^10
    int g  = gidx[k];

    int4   q = reinterpret_cast<const int4*>(qw + (size_t)k * ND)[n4];
    int4   z = reinterpret_cast<const int4*>(zp + (size_t)g * ND)[n4];
    float4 s = reinterpret_cast<const float4*>(sc + (size_t)g * ND)[n4];

    float4 w;
    w.x = s.x * (float)(q.x - z.x);
    w.y = s.y * (float)(q.y - z.y);
    w.z = s.z * (float)(q.z - z.z);
    w.w = s.w * (float)(q.w - z.w);

    reinterpret_cast<float4*>(g_W + (size_t)k * ND)[n4] = w;
}

// ---------------------------------------------------------------------------
// fp32 SIMT SGEMM: C[m][n] = sum_k A[m][k] * W[k][n] + bias[n]
// BM=BN=128, BK=8, 256 threads, 8x8 micro-tile per thread.
// ---------------------------------------------------------------------------
static constexpr int BM = 128;
static constexpr int BN = 128;
static constexpr int BK = 8;
static constexpr int TM = 8;
static constexpr int TN = 8;

__global__ __launch_bounds__(256) void sgemm_kernel(
    const float* __restrict__ A,     // [M, KD]
    const float* __restrict__ bias,  // [ND]
    float* __restrict__ C)           // [M, ND]
{
    __shared__ float As[BK][BM];     // A tile, transposed (k-major)
    __shared__ float Bs[BK][BN];     // W tile

    const int t  = threadIdx.x;          // 0..255
    const int tx = t & 15;               // 16 threads across N
    const int ty = t >> 4;               // 16 threads across M
    const int m0 = blockIdx.y * BM;
    const int n0 = blockIdx.x * BN;

    // Global-load assignments (one float4 per thread per tile)
    const int arow = t >> 1;             // 0..127 : A row within tile
    const int acol = (t & 1) * 4;        // 0 or 4 : A k-offset
    const int brow = t >> 5;             // 0..7   : W k-row within tile
    const int bcol = (t & 31) * 4;       // 0..124 : W n-offset

    const float* Aptr = A + (size_t)(m0 + arow) * KD + acol;
    const float* Bptr = g_W + (size_t)brow * ND + n0 + bcol;

    float acc[TM][TN];
    #pragma unroll
    for (int i = 0; i < TM; i++)
        #pragma unroll
        for (int j = 0; j < TN; j++)
            acc[i][j] = 0.0f;

    for (int k0 = 0; k0 < KD; k0 += BK) {
        // Load A tile (transposed into shared) and W tile
        float4 av = *reinterpret_cast<const float4*>(Aptr + k0);
        As[acol + 0][arow] = av.x;
        As[acol + 1][arow] = av.y;
        As[acol + 2][arow] = av.z;
        As[acol + 3][arow] = av.w;

        float4 bv = *reinterpret_cast<const float4*>(Bptr + (size_t)k0 * ND);
        *reinterpret_cast<float4*>(&Bs[brow][bcol]) = bv;

        __syncthreads();

        #pragma unroll
        for (int kk = 0; kk < BK; kk++) {
            float a[TM], b[TN];
            #pragma unroll
            for (int i = 0; i < TM; i++) a[i] = As[kk][ty * TM + i];
            #pragma unroll
            for (int j = 0; j < TN; j++) b[j] = Bs[kk][tx * TN + j];
            #pragma unroll
            for (int i = 0; i < TM; i++)
                #pragma unroll
                for (int j = 0; j < TN; j++)
                    acc[i][j] = fmaf(a[i], b[j], acc[i][j]);
        }

        __syncthreads();
    }

    // Epilogue: bias + store (vectorized)
    const int ncol = n0 + tx * TN;
    float4 b0 = *reinterpret_cast<const float4*>(bias + ncol);
    float4 b1 = *reinterpret_cast<const float4*>(bias + ncol + 4);

    #pragma unroll
    for (int i = 0; i < TM; i++) {
        const size_t row = (size_t)(m0 + ty * TM + i);
        float4 o0, o1;
        o0.x = acc[i][0] + b0.x;
        o0.y = acc[i][1] + b0.y;
        o0.z = acc[i][2] + b0.z;
        o0.w = acc[i][3] + b0.w;
        o1.x = acc[i][4] + b1.x;
        o1.y = acc[i][5] + b1.y;
        o1.z = acc[i][6] + b1.z;
        o1.w = acc[i][7] + b1.w;
        *reinterpret_cast<float4*>(C + row * ND + ncol)     = o0;
        *reinterpret_cast<float4*>(C + row * ND + ncol + 4) = o1;
    }
}

// ---------------------------------------------------------------------------
// Launch. Inputs (metadata order): x, qweight_int, scales, zero_points,
// g_idx, bias. Output: fp32 [b, s, ND].
// ---------------------------------------------------------------------------
extern "C" void kernel_launch(void* const* d_in, const int* in_sizes, int n_in,
                              void* d_out, int out_size)
{
    const float* x    = (const float*)d_in[0];
    const int*   qw   = (const int*)  d_in[1];
    const float* sc   = (const float*)d_in[2];
    const int*   zp   = (const int*)  d_in[3];
    const int*   gidx = (const int*)  d_in[4];
    const float* bias = (const float*)d_in[5];
    float*       out  = (float*)d_out;

    const int M = in_sizes[0] / KD;   // 2*2048 = 4096 tokens

    // 1) Dequantize weights into g_W
    const int dq_threads = 256;
    const int dq_blocks  = (KD * (ND / 4)) / dq_threads;   // 16384
    dequant_kernel<<<dq_blocks, dq_threads>>>(qw, sc, zp, gidx);

    // 2) GEMM + bias
    dim3 grid(ND / BN, M / BM);   // (32, 32)
    sgemm_kernel<<<grid, 256>>>(x, bias, out);
}

// round 5
// speedup vs baseline: 3.0361x; 3.0361x over previous
#include <cuda_runtime.h>
#include <cuda_bf16.h>
#include <cstdint>

// ---------------------------------------------------------------------------
// Problem constants
// ---------------------------------------------------------------------------
static constexpr int KD = 4096;
static constexpr int ND = 4096;
static constexpr int MD = 4096;

// GEMM tiling
static constexpr int BM = 128;
static constexpr int BN = 128;
static constexpr int BK = 32;
static constexpr int STAGES = 3;
static constexpr int NCHUNK = KD / BK;   // 128
static constexpr int THREADS = 256;

// SMEM stage layout (padded rows -> conflict-reduced ldmatrix phases)
static constexpr int A_ROWB = 80;              // 64B data + 16B pad
static constexpr int B_ROWB = 272;             // 256B data + 16B pad
static constexpr int SZ_A = BM * A_ROWB;       // 10240
static constexpr int SZ_B = BK * B_ROWB;       // 8704
static constexpr int OFF_AH = 0;
static constexpr int OFF_AL = SZ_A;
static constexpr int OFF_BH = 2 * SZ_A;
static constexpr int OFF_BL = 2 * SZ_A + SZ_B;
static constexpr int STAGE_BYTES = 2 * SZ_A + 2 * SZ_B;   // 37888
static constexpr int SMEM_TOTAL = STAGES * STAGE_BYTES;   // 113664

// ---------------------------------------------------------------------------
// Scratch: split bf16 operands. A (x) [M,K]; B (W) [K,N] (natural layout).
// ---------------------------------------------------------------------------
__device__ __nv_bfloat16 g_Ah[(size_t)MD * KD];
__device__ __nv_bfloat16 g_Al[(size_t)MD * KD];
__device__ __nv_bfloat16 g_Bh[(size_t)KD * ND];
__device__ __nv_bfloat16 g_Bl[(size_t)KD * ND];

// ---------------------------------------------------------------------------
// PTX helpers (sm_80-era: valid on compute_103 virtual target)
// ---------------------------------------------------------------------------
__device__ __forceinline__ uint32_t smem_u32(const void* p) {
    uint32_t a;
    asm("{ .reg .u64 t; cvta.to.shared.u64 t, %1; cvt.u32.u64 %0, t; }" : "=r"(a) : "l"(p));
    return a;
}
__device__ __forceinline__ void cp_async16(uint32_t dst, const void* src) {
    asm volatile("cp.async.cg.shared.global [%0], [%1], 16;" :: "r"(dst), "l"(src));
}
__device__ __forceinline__ void cp_commit() {
    asm volatile("cp.async.commit_group;" ::: "memory");
}
__device__ __forceinline__ void ldsm4(uint32_t* r, uint32_t addr) {
    asm volatile("ldmatrix.sync.aligned.m8n8.x4.shared.b16 {%0,%1,%2,%3}, [%4];"
                 : "=r"(r[0]), "=r"(r[1]), "=r"(r[2]), "=r"(r[3]) : "r"(addr));
}
__device__ __forceinline__ void ldsm4t(uint32_t* r, uint32_t addr) {
    asm volatile("ldmatrix.sync.aligned.m8n8.x4.trans.shared.b16 {%0,%1,%2,%3}, [%4];"
                 : "=r"(r[0]), "=r"(r[1]), "=r"(r[2]), "=r"(r[3]) : "r"(addr));
}
__device__ __forceinline__ void mma_bf16(float* c, const uint32_t* a, const uint32_t* b) {
    asm volatile(
        "mma.sync.aligned.m16n8k16.row.col.f32.bf16.bf16.f32 "
        "{%0,%1,%2,%3}, {%4,%5,%6,%7}, {%8,%9}, {%0,%1,%2,%3};"
        : "+f"(c[0]), "+f"(c[1]), "+f"(c[2]), "+f"(c[3])
        : "r"(a[0]), "r"(a[1]), "r"(a[2]), "r"(a[3]), "r"(b[0]), "r"(b[1]));
}

// ---------------------------------------------------------------------------
// Prep 1: split x (fp32 [M,K]) into bf16 hi/lo
// ---------------------------------------------------------------------------
__global__ __launch_bounds__(256) void split_x_kernel(const float* __restrict__ x) {
    size_t i = (size_t)blockIdx.x * 256 + threadIdx.x;   // over M*K/4
    float4 v = reinterpret_cast<const float4*>(x)[i];

    __nv_bfloat16 h0 = __float2bfloat16(v.x), h1 = __float2bfloat16(v.y);
    __nv_bfloat16 h2 = __float2bfloat16(v.z), h3 = __float2bfloat16(v.w);
    __nv_bfloat16 l0 = __float2bfloat16(v.x - __bfloat162float(h0));
    __nv_bfloat16 l1 = __float2bfloat16(v.y - __bfloat162float(h1));
    __nv_bfloat16 l2 = __float2bfloat16(v.z - __bfloat162float(h2));
    __nv_bfloat16 l3 = __float2bfloat16(v.w - __bfloat162float(h3));

    reinterpret_cast<__nv_bfloat162*>(g_Ah)[i * 2 + 0] = __nv_bfloat162(h0, h1);
    reinterpret_cast<__nv_bfloat162*>(g_Ah)[i * 2 + 1] = __nv_bfloat162(h2, h3);
    reinterpret_cast<__nv_bfloat162*>(g_Al)[i * 2 + 0] = __nv_bfloat162(l0, l1);
    reinterpret_cast<__nv_bfloat162*>(g_Al)[i * 2 + 1] = __nv_bfloat162(l2, l3);
}

// ---------------------------------------------------------------------------
// Prep 2: dequant W[k][n] = sc[g][n]*(q[k][n]-zp[g][n]) -> bf16 hi/lo [K,N]
// ---------------------------------------------------------------------------
__global__ __launch_bounds__(256) void dequant_kernel(
    const int* __restrict__ qw, const float* __restrict__ sc,
    const int* __restrict__ zp, const int* __restrict__ gidx) {
    size_t idx = (size_t)blockIdx.x * 256 + threadIdx.x;   // over K*N/4
    int n4 = (int)(idx & (ND / 4 - 1));
    int k  = (int)(idx >> 10);
    int g  = gidx[k];

    int4   q = reinterpret_cast<const int4*>(qw + (size_t)k * ND)[n4];
    int4   z = reinterpret_cast<const int4*>(zp + (size_t)g * ND)[n4];
    float4 s = reinterpret_cast<const float4*>(sc + (size_t)g * ND)[n4];

    float w0 = s.x * (float)(q.x - z.x);
    float w1 = s.y * (float)(q.y - z.y);
    float w2 = s.z * (float)(q.z - z.z);
    float w3 = s.w * (float)(q.w - z.w);

    __nv_bfloat16 h0 = __float2bfloat16(w0), h1 = __float2bfloat16(w1);
    __nv_bfloat16 h2 = __float2bfloat16(w2), h3 = __float2bfloat16(w3);
    __nv_bfloat16 l0 = __float2bfloat16(w0 - __bfloat162float(h0));
    __nv_bfloat16 l1 = __float2bfloat16(w1 - __bfloat162float(h1));
    __nv_bfloat16 l2 = __float2bfloat16(w2 - __bfloat162float(h2));
    __nv_bfloat16 l3 = __float2bfloat16(w3 - __bfloat162float(h3));

    reinterpret_cast<__nv_bfloat162*>(g_Bh)[idx * 2 + 0] = __nv_bfloat162(h0, h1);
    reinterpret_cast<__nv_bfloat162*>(g_Bh)[idx * 2 + 1] = __nv_bfloat162(h2, h3);
    reinterpret_cast<__nv_bfloat162*>(g_Bl)[idx * 2 + 0] = __nv_bfloat162(l0, l1);
    reinterpret_cast<__nv_bfloat162*>(g_Bl)[idx * 2 + 1] = __nv_bfloat162(l2, l3);
}

// ---------------------------------------------------------------------------
// GEMM: C = x @ W + bias via split-bf16 mma.sync, 3-stage cp.async pipeline
// ---------------------------------------------------------------------------
__device__ __forceinline__ void load_stage(uint32_t sbase, int chunk,
                                           int m0, int n0, int t) {
    const int k0 = chunk * BK;
    // A tiles: 128 rows x 4 segs of 16B = 512 segments each (hi and lo)
    #pragma unroll
    for (int u = 0; u < 2; u++) {
        int idx = t + u * THREADS;        // 0..511
        int row = idx >> 2, seg = idx & 3;
        uint32_t so = row * A_ROWB + seg * 16;
        size_t go = (size_t)(m0 + row) * KD + k0 + seg * 8;
        cp_async16(sbase + OFF_AH + so, g_Ah + go);
        cp_async16(sbase + OFF_AL + so, g_Al + go);
    }
    // B tiles: 32 rows x 16 segs of 16B = 512 segments each (hi and lo)
    #pragma unroll
    for (int u = 0; u < 2; u++) {
        int idx = t + u * THREADS;        // 0..511
        int row = idx >> 4, seg = idx & 15;
        uint32_t so = row * B_ROWB + seg * 16;
        size_t go = (size_t)(k0 + row) * ND + n0 + seg * 8;
        cp_async16(sbase + OFF_BH + so, g_Bh + go);
        cp_async16(sbase + OFF_BL + so, g_Bl + go);
    }
}

__global__ __launch_bounds__(THREADS, 1) void gemm_kernel(
    const float* __restrict__ bias, float* __restrict__ C) {
    extern __shared__ char smem[];
    const uint32_t sb = smem_u32(smem);
    const int t = threadIdx.x;
    const int lane = t & 31;
    const int wid = t >> 5;
    const int wm = wid >> 2;         // 0..1  (64-row slice)
    const int wn = wid & 3;          // 0..3  (32-col slice)
    const int m0 = blockIdx.y * BM;
    const int n0 = blockIdx.x * BN;

    // ldmatrix per-thread base offsets
    const uint32_t a_off0 = (uint32_t)(wm * 64 + (lane & 15)) * A_ROWB + (lane >> 4) * 16;
    const uint32_t b_off0 = (uint32_t)(lane & 15) * B_ROWB + wn * 64 + (lane >> 4) * 16;

    float acc[4][4][4];
    #pragma unroll
    for (int f = 0; f < 4; f++)
        #pragma unroll
        for (int n = 0; n < 4; n++)
            #pragma unroll
            for (int e = 0; e < 4; e++)
                acc[f][n][e] = 0.0f;

    // Prologue: stages 0, 1
    load_stage(sb + 0 * STAGE_BYTES, 0, m0, n0, t);
    cp_commit();
    load_stage(sb + 1 * STAGE_BYTES, 1, m0, n0, t);
    cp_commit();

    int slot = 0;
    for (int c = 0; c < NCHUNK; c++) {
        asm volatile("cp.async.wait_group 1;" ::: "memory");
        __syncthreads();

        // Prefetch a REAL group every iteration (redundant reload of the last
        // chunk in the tail keeps wait_group depth accounting exact).
        {
            int pc = (c + 2 < NCHUNK) ? (c + 2) : (NCHUNK - 1);
            int ns = slot + 2; if (ns >= STAGES) ns -= STAGES;
            load_stage(sb + ns * STAGE_BYTES, pc, m0, n0, t);
            cp_commit();
        }

        const uint32_t stage = sb + slot * STAGE_BYTES;

        #pragma unroll
        for (int ks = 0; ks < 2; ks++) {
            uint32_t Ah[4][4], Al[4][4], Bh[4][2], Bl[4][2];
            #pragma unroll
            for (int f = 0; f < 4; f++) {
                uint32_t ao = a_off0 + f * 16 * A_ROWB + ks * 32;
                ldsm4(Ah[f], stage + OFF_AH + ao);
                ldsm4(Al[f], stage + OFF_AL + ao);
            }
            #pragma unroll
            for (int p = 0; p < 2; p++) {
                uint32_t bo = b_off0 + ks * 16 * B_ROWB + p * 32;
                uint32_t tmp[4];
                ldsm4t(tmp, stage + OFF_BH + bo);
                Bh[2 * p][0] = tmp[0]; Bh[2 * p][1] = tmp[1];
                Bh[2 * p + 1][0] = tmp[2]; Bh[2 * p + 1][1] = tmp[3];
                ldsm4t(tmp, stage + OFF_BL + bo);
                Bl[2 * p][0] = tmp[0]; Bl[2 * p][1] = tmp[1];
                Bl[2 * p + 1][0] = tmp[2]; Bl[2 * p + 1][1] = tmp[3];
            }
            // term hi*hi
            #pragma unroll
            for (int f = 0; f < 4; f++)
                #pragma unroll
                for (int n = 0; n < 4; n++)
                    mma_bf16(acc[f][n], Ah[f], Bh[n]);
            // term hi*lo
            #pragma unroll
            for (int f = 0; f < 4; f++)
                #pragma unroll
                for (int n = 0; n < 4; n++)
                    mma_bf16(acc[f][n], Ah[f], Bl[n]);
            // term lo*hi
            #pragma unroll
            for (int f = 0; f < 4; f++)
                #pragma unroll
                for (int n = 0; n < 4; n++)
                    mma_bf16(acc[f][n], Al[f], Bh[n]);
        }

        __syncthreads();
        slot++; if (slot >= STAGES) slot = 0;
    }

    // Epilogue: bias + store
    const int row0 = lane >> 2;
    const int col0 = (lane & 3) * 2;
    #pragma unroll
    for (int n = 0; n < 4; n++) {
        const int gc = n0 + wn * 32 + n * 8 + col0;
        const float2 bb = *reinterpret_cast<const float2*>(bias + gc);
        #pragma unroll
        for (int f = 0; f < 4; f++) {
            const int gr = m0 + wm * 64 + f * 16 + row0;
            float2 o0, o1;
            o0.x = acc[f][n][0] + bb.x;
            o0.y = acc[f][n][1] + bb.y;
            o1.x = acc[f][n][2] + bb.x;
            o1.y = acc[f][n][3] + bb.y;
            *reinterpret_cast<float2*>(C + (size_t)gr * ND + gc) = o0;
            *reinterpret_cast<float2*>(C + (size_t)(gr + 8) * ND + gc) = o1;
        }
    }
}

// ---------------------------------------------------------------------------
// Launch. Inputs: x, qweight_int, scales, zero_points, g_idx, bias. Out: fp32.
// ---------------------------------------------------------------------------
extern "C" void kernel_launch(void* const* d_in, const int* in_sizes, int n_in,
                              void* d_out, int out_size) {
    const float* x    = (const float*)d_in[0];
    const int*   qw   = (const int*)  d_in[1];
    const float* sc   = (const float*)d_in[2];
    const int*   zp   = (const int*)  d_in[3];
    const int*   gidx = (const int*)  d_in[4];
    const float* bias = (const float*)d_in[5];
    float*       out  = (float*)d_out;

    const int M = in_sizes[0] / KD;   // 4096

    cudaFuncSetAttribute(gemm_kernel,
                         cudaFuncAttributeMaxDynamicSharedMemorySize, SMEM_TOTAL);

    split_x_kernel<<<(M * KD / 4) / 256, 256>>>(x);
    dequant_kernel<<<(KD * (ND / 4)) / 256, 256>>>(qw, sc, zp, gidx);
    gemm_kernel<<<dim3(ND / BN, M / BM), THREADS, SMEM_TOTAL>>>(bias, out);
}

// round 8
// speedup vs baseline: 3.9684x; 1.3071x over previous
#include <cuda_runtime.h>
#include <cuda_bf16.h>
#include <cstdint>

// ---------------------------------------------------------------------------
// Problem constants
// ---------------------------------------------------------------------------
static constexpr int KD = 4096;
static constexpr int ND = 4096;
static constexpr int MD = 4096;
static constexpr int NGROUPS = 32;       // K groups of 128

// GEMM tiling
static constexpr int BM = 128;
static constexpr int BN = 128;
static constexpr int BK = 32;
static constexpr int STAGES = 4;
static constexpr int NCHUNK = KD / BK;   // 128 ; group = 4 chunks
static constexpr int THREADS = 256;

// SMEM stage layout (padded rows -> conflict-reduced ldmatrix phases)
static constexpr int A_ROWB = 80;              // 64B data + 16B pad
static constexpr int B_ROWB = 272;             // 256B data + 16B pad
static constexpr int SZ_A = BM * A_ROWB;       // 10240
static constexpr int SZ_B = BK * B_ROWB;       // 8704
static constexpr int OFF_AH = 0;
static constexpr int OFF_AL = SZ_A;
static constexpr int OFF_BD = 2 * SZ_A;
static constexpr int STAGE_BYTES = 2 * SZ_A + SZ_B;            // 29184
static constexpr int SC_BYTES = NGROUPS * BN * 4;              // 16384
static constexpr int SMEM_TOTAL = SC_BYTES + STAGES * STAGE_BYTES;  // 133120

// ---------------------------------------------------------------------------
// Scratch: A (x) split bf16 hi/lo [M,K]; B = (q - zp) exact ints as bf16 [K,N]
// ---------------------------------------------------------------------------
__device__ __nv_bfloat16 g_Ah[(size_t)MD * KD];
__device__ __nv_bfloat16 g_Al[(size_t)MD * KD];
__device__ __nv_bfloat16 g_Bd[(size_t)KD * ND];

// ---------------------------------------------------------------------------
// PTX helpers
// ---------------------------------------------------------------------------
__device__ __forceinline__ uint32_t smem_u32(const void* p) {
    uint32_t a;
    asm("{ .reg .u64 t; cvta.to.shared.u64 t, %1; cvt.u32.u64 %0, t; }" : "=r"(a) : "l"(p));
    return a;
}
__device__ __forceinline__ void cp_async16(uint32_t dst, const void* src) {
    asm volatile("cp.async.cg.shared.global [%0], [%1], 16;" :: "r"(dst), "l"(src));
}
__device__ __forceinline__ void cp_commit() {
    asm volatile("cp.async.commit_group;" ::: "memory");
}
__device__ __forceinline__ void ldsm4(uint32_t* r, uint32_t addr) {
    asm volatile("ldmatrix.sync.aligned.m8n8.x4.shared.b16 {%0,%1,%2,%3}, [%4];"
                 : "=r"(r[0]), "=r"(r[1]), "=r"(r[2]), "=r"(r[3]) : "r"(addr));
}
__device__ __forceinline__ void ldsm4t(uint32_t* r, uint32_t addr) {
    asm volatile("ldmatrix.sync.aligned.m8n8.x4.trans.shared.b16 {%0,%1,%2,%3}, [%4];"
                 : "=r"(r[0]), "=r"(r[1]), "=r"(r[2]), "=r"(r[3]) : "r"(addr));
}
__device__ __forceinline__ void mma_bf16(float* c, const uint32_t* a, const uint32_t* b) {
    asm volatile(
        "mma.sync.aligned.m16n8k16.row.col.f32.bf16.bf16.f32 "
        "{%0,%1,%2,%3}, {%4,%5,%6,%7}, {%8,%9}, {%0,%1,%2,%3};"
        : "+f"(c[0]), "+f"(c[1]), "+f"(c[2]), "+f"(c[3])
        : "r"(a[0]), "r"(a[1]), "r"(a[2]), "r"(a[3]), "r"(b[0]), "r"(b[1]));
}

// ---------------------------------------------------------------------------
// Prep 1: split x (fp32 [M,K]) into bf16 hi/lo
// ---------------------------------------------------------------------------
__global__ __launch_bounds__(256) void split_x_kernel(const float* __restrict__ x) {
    size_t i = (size_t)blockIdx.x * 256 + threadIdx.x;   // over M*K/4
    float4 v = reinterpret_cast<const float4*>(x)[i];

    __nv_bfloat16 h0 = __float2bfloat16(v.x), h1 = __float2bfloat16(v.y);
    __nv_bfloat16 h2 = __float2bfloat16(v.z), h3 = __float2bfloat16(v.w);
    __nv_bfloat16 l0 = __float2bfloat16(v.x - __bfloat162float(h0));
    __nv_bfloat16 l1 = __float2bfloat16(v.y - __bfloat162float(h1));
    __nv_bfloat16 l2 = __float2bfloat16(v.z - __bfloat162float(h2));
    __nv_bfloat16 l3 = __float2bfloat16(v.w - __bfloat162float(h3));

    reinterpret_cast<__nv_bfloat162*>(g_Ah)[i * 2 + 0] = __nv_bfloat162(h0, h1);
    reinterpret_cast<__nv_bfloat162*>(g_Ah)[i * 2 + 1] = __nv_bfloat162(h2, h3);
    reinterpret_cast<__nv_bfloat162*>(g_Al)[i * 2 + 0] = __nv_bfloat162(l0, l1);
    reinterpret_cast<__nv_bfloat162*>(g_Al)[i * 2 + 1] = __nv_bfloat162(l2, l3);
}

// ---------------------------------------------------------------------------
// Prep 2: d[k][n] = q[k][n] - zp[g(k)][n]  (small int, EXACT in bf16)
// ---------------------------------------------------------------------------
__global__ __launch_bounds__(256) void diff_kernel(
    const int* __restrict__ qw, const int* __restrict__ zp,
    const int* __restrict__ gidx) {
    size_t idx = (size_t)blockIdx.x * 256 + threadIdx.x;   // over K*N/4
    int n4 = (int)(idx & (ND / 4 - 1));
    int k  = (int)(idx >> 10);
    int g  = gidx[k];

    int4 q = reinterpret_cast<const int4*>(qw + (size_t)k * ND)[n4];
    int4 z = reinterpret_cast<const int4*>(zp + (size_t)g * ND)[n4];

    __nv_bfloat16 d0 = __float2bfloat16((float)(q.x - z.x));
    __nv_bfloat16 d1 = __float2bfloat16((float)(q.y - z.y));
    __nv_bfloat16 d2 = __float2bfloat16((float)(q.z - z.z));
    __nv_bfloat16 d3 = __float2bfloat16((float)(q.w - z.w));

    reinterpret_cast<__nv_bfloat162*>(g_Bd)[idx * 2 + 0] = __nv_bfloat162(d0, d1);
    reinterpret_cast<__nv_bfloat162*>(g_Bd)[idx * 2 + 1] = __nv_bfloat162(d2, d3);
}

// ---------------------------------------------------------------------------
// GEMM: C = x @ (sc * d) + bias ; scales factored out per K-group.
// ---------------------------------------------------------------------------
__device__ __forceinline__ void load_stage(uint32_t sbase, int chunk,
                                           int m0, int n0, int t) {
    const int k0 = chunk * BK;
    // A tiles: 128 rows x 4 segs of 16B = 512 segments each (hi and lo)
    #pragma unroll
    for (int u = 0; u < 2; u++) {
        int idx = t + u * THREADS;        // 0..511
        int row = idx >> 2, seg = idx & 3;
        uint32_t so = row * A_ROWB + seg * 16;
        size_t go = (size_t)(m0 + row) * KD + k0 + seg * 8;
        cp_async16(sbase + OFF_AH + so, g_Ah + go);
        cp_async16(sbase + OFF_AL + so, g_Al + go);
    }
    // B tile: 32 rows x 16 segs of 16B = 512 segments
    #pragma unroll
    for (int u = 0; u < 2; u++) {
        int idx = t + u * THREADS;        // 0..511
        int row = idx >> 4, seg = idx & 15;
        uint32_t so = row * B_ROWB + seg * 16;
        size_t go = (size_t)(k0 + row) * ND + n0 + seg * 8;
        cp_async16(sbase + OFF_BD + so, g_Bd + go);
    }
}

__global__ __launch_bounds__(THREADS, 1) void gemm_kernel(
    const float* __restrict__ scales,   // [NGROUPS, ND]
    const float* __restrict__ bias, float* __restrict__ C) {
    extern __shared__ char smem[];
    const uint32_t sb = smem_u32(smem);
    float* scs = reinterpret_cast<float*>(smem);          // [NGROUPS][BN]
    const uint32_t stage0 = sb + SC_BYTES;

    const int t = threadIdx.x;
    const int lane = t & 31;
    const int wid = t >> 5;
    const int wm = wid >> 2;         // 0..1  (64-row slice)
    const int wn = wid & 3;          // 0..3  (32-col slice)
    const int m0 = blockIdx.y * BM;
    const int n0 = blockIdx.x * BN;

    // Preload the 32x128 scale slab for this CTA's columns (plain loads).
    #pragma unroll
    for (int u = 0; u < 4; u++) {
        int i = t + u * THREADS;           // 0..1023 float4s
        int g = i >> 5, j4 = i & 31;
        reinterpret_cast<float4*>(scs)[(size_t)g * 32 + j4] =
            *reinterpret_cast<const float4*>(scales + (size_t)g * ND + n0 + j4 * 4);
    }

    // ldmatrix per-thread base offsets
    const uint32_t a_off0 = (uint32_t)(wm * 64 + (lane & 15)) * A_ROWB + (lane >> 4) * 16;
    const uint32_t b_off0 = (uint32_t)(lane & 15) * B_ROWB + wn * 64 + (lane >> 4) * 16;

    float master[4][4][4];
    float part[4][4][4];
    #pragma unroll
    for (int f = 0; f < 4; f++)
        #pragma unroll
        for (int n = 0; n < 4; n++)
            #pragma unroll
            for (int e = 0; e < 4; e++) {
                master[f][n][e] = 0.0f;
                part[f][n][e] = 0.0f;
            }

    // Prologue: stages 0..2
    load_stage(stage0 + 0 * STAGE_BYTES, 0, m0, n0, t);
    cp_commit();
    load_stage(stage0 + 1 * STAGE_BYTES, 1, m0, n0, t);
    cp_commit();
    load_stage(stage0 + 2 * STAGE_BYTES, 2, m0, n0, t);
    cp_commit();

    const int col0 = (lane & 3) * 2;

    for (int c = 0; c < NCHUNK; c++) {
        const int slot = c & 3;
        asm volatile("cp.async.wait_group 2;" ::: "memory");
        __syncthreads();   // also guarantees prior-iter reads of slot (c+3)&3 done

        // Prefetch one REAL group every iteration (dup reload of last chunk in
        // the tail keeps wait_group depth accounting exact).
        {
            int pc = (c + 3 < NCHUNK) ? (c + 3) : (NCHUNK - 1);
            load_stage(stage0 + ((c + 3) & 3) * STAGE_BYTES, pc, m0, n0, t);
            cp_commit();
        }

        const uint32_t stage = stage0 + slot * STAGE_BYTES;

        #pragma unroll
        for (int ks = 0; ks < 2; ks++) {
            uint32_t Ah[4][4], Al[4][4], Bd[4][2];
            #pragma unroll
            for (int f = 0; f < 4; f++) {
                uint32_t ao = a_off0 + f * 16 * A_ROWB + ks * 32;
                ldsm4(Ah[f], stage + OFF_AH + ao);
                ldsm4(Al[f], stage + OFF_AL + ao);
            }
            #pragma unroll
            for (int p = 0; p < 2; p++) {
                uint32_t bo = b_off0 + ks * 16 * B_ROWB + p * 32;
                uint32_t tmp[4];
                ldsm4t(tmp, stage + OFF_BD + bo);
                Bd[2 * p][0] = tmp[0]; Bd[2 * p][1] = tmp[1];
                Bd[2 * p + 1][0] = tmp[2]; Bd[2 * p + 1][1] = tmp[3];
            }
            #pragma unroll
            for (int f = 0; f < 4; f++)
                #pragma unroll
                for (int n = 0; n < 4; n++)
                    mma_bf16(part[f][n], Ah[f], Bd[n]);
            #pragma unroll
            for (int f = 0; f < 4; f++)
                #pragma unroll
                for (int n = 0; n < 4; n++)
                    mma_bf16(part[f][n], Al[f], Bd[n]);
        }

        // End of a K-group (4 chunks): fold scaled partials into master.
        if ((c & 3) == 3) {
            const int g = c >> 2;
            #pragma unroll
            for (int n = 0; n < 4; n++) {
                const float2 s2 = *reinterpret_cast<const float2*>(
                    scs + (size_t)g * BN + wn * 32 + n * 8 + col0);
                #pragma unroll
                for (int f = 0; f < 4; f++) {
                    master[f][n][0] += s2.x * part[f][n][0];
                    master[f][n][1] += s2.y * part[f][n][1];
                    master[f][n][2] += s2.x * part[f][n][2];
                    master[f][n][3] += s2.y * part[f][n][3];
                    part[f][n][0] = 0.0f; part[f][n][1] = 0.0f;
                    part[f][n][2] = 0.0f; part[f][n][3] = 0.0f;
                }
            }
        }
    }

    // Epilogue: bias + store
    const int row0 = lane >> 2;
    #pragma unroll
    for (int n = 0; n < 4; n++) {
        const int gc = n0 + wn * 32 + n * 8 + col0;
        const float2 bb = *reinterpret_cast<const float2*>(bias + gc);
        #pragma unroll
        for (int f = 0; f < 4; f++) {
            const int gr = m0 + wm * 64 + f * 16 + row0;
            float2 o0, o1;
            o0.x = master[f][n][0] + bb.x;
            o0.y = master[f][n][1] + bb.y;
            o1.x = master[f][n][2] + bb.x;
            o1.y = master[f][n][3] + bb.y;
            *reinterpret_cast<float2*>(C + (size_t)gr * ND + gc) = o0;
            *reinterpret_cast<float2*>(C + (size_t)(gr + 8) * ND + gc) = o1;
        }
    }
}

// ---------------------------------------------------------------------------
// Launch. Inputs: x, qweight_int, scales, zero_points, g_idx, bias. Out: fp32.
// ---------------------------------------------------------------------------
extern "C" void kernel_launch(void* const* d_in, const int* in_sizes, int n_in,
                              void* d_out, int out_size) {
    const float* x    = (const float*)d_in[0];
    const int*   qw   = (const int*)  d_in[1];
    const float* sc   = (const float*)d_in[2];
    const int*   zp   = (const int*)  d_in[3];
    const int*   gidx = (const int*)  d_in[4];
    const float* bias = (const float*)d_in[5];
    float*       out  = (float*)d_out;

    const int M = in_sizes[0] / KD;   // 4096

    cudaFuncSetAttribute(gemm_kernel,
                         cudaFuncAttributeMaxDynamicSharedMemorySize, SMEM_TOTAL);

    split_x_kernel<<<(M * KD / 4) / 256, 256>>>(x);
    diff_kernel<<<(KD * (ND / 4)) / 256, 256>>>(qw, zp, gidx);
    gemm_kernel<<<dim3(ND / BN, M / BM), THREADS, SMEM_TOTAL>>>(sc, bias, out);
}